// round 5
// baseline (speedup 1.0000x reference)
#include <cuda_runtime.h>
#include <cuda_fp16.h>
#include <cstdint>

#define SS 2048
#define BB 64
#define DD 512

// ---------------- device scratch (static; no runtime allocs) ----------------
__device__ float g_u[BB * DD];                      // u[b,a] = input.W1x + b1
__device__ __align__(16) __half g_whi[DD * DD];     // W1_src hi (fp16), K-major [a][d]
__device__ __align__(16) __half g_wlo[DD * DD];     // W1_src residual (fp16)
__device__ float g_part[8 * BB * DD];               // ctx partials (8 s-slices)

// ---------------- helpers ----------------
__device__ __forceinline__ uint32_t smem_u32(const void* p) {
    uint32_t a;
    asm("{ .reg .u64 t; cvta.to.shared.u64 t, %1; cvt.u32.u64 %0, t; }" : "=r"(a) : "l"(p));
    return a;
}
__device__ __forceinline__ uint32_t packh2(__half a, __half b) {
    __half2 h = __halves2half2(a, b);
    return *reinterpret_cast<uint32_t*>(&h);
}
__device__ __forceinline__ void cp16(uint32_t dst, const void* src) {
    asm volatile("cp.async.cg.shared.global [%0], [%1], 16;" :: "r"(dst), "l"(src) : "memory");
}
__device__ __forceinline__ float tanh_f(float x) {
    float e = __expf(2.f * x);
    return 1.f - __fdividef(2.f, e + 1.f);
}

#define LDSM4(r, addr) \
    asm volatile("ldmatrix.sync.aligned.m8n8.x4.shared.b16 {%0,%1,%2,%3}, [%4];" \
        : "=r"((r)[0]), "=r"((r)[1]), "=r"((r)[2]), "=r"((r)[3]) : "r"(addr))

#define MMA(d, a, b) \
    asm volatile("mma.sync.aligned.m16n8k16.row.col.f32.f16.f16.f32 " \
        "{%0,%1,%2,%3}, {%4,%5,%6,%7}, {%8,%9}, {%0,%1,%2,%3};" \
        : "+f"((d)[0]), "+f"((d)[1]), "+f"((d)[2]), "+f"((d)[3]) \
        : "r"((a)[0]), "r"((a)[1]), "r"((a)[2]), "r"((a)[3]), "r"((b)[0]), "r"((b)[1]))

// ---------------- smem layout for gemm_k ----------------
#define U_OFF    0
#define W2_OFF   2048
#define RED_OFF  4096
#define TILE_OFF 5120
#define ROWB     80           // 64B data + 16B pad -> conflict-free ldmatrix
#define A_O      0            // 128 rows x 32 half
#define BHI_O    10240        // 128 rows x 32 half
#define BLO_O    20480
#define ST_SZ    30720
#define DYN_SMEM (TILE_OFF + 2 * ST_SZ)   // 66560

// ==================== prep: u[b,a] and W fp16 hi/lo split ====================
__global__ void prep_k(const float* __restrict__ input, const float* __restrict__ W1,
                       const float* __restrict__ b1) {
    __shared__ float inp[DD];
    int blk = blockIdx.x, tid = threadIdx.x;
    if (blk < BB) {
        inp[tid] = input[blk * DD + tid];
        inp[tid + 256] = input[blk * DD + tid + 256];
        __syncthreads();
        for (int a = tid; a < DD; a += 256) {
            const float* w = W1 + (size_t)a * (2 * DD);
            float acc = b1[a];
            #pragma unroll 8
            for (int d = 0; d < DD; d++) acc += inp[d] * w[d];
            g_u[blk * DD + a] = acc;
        }
    } else {
        int base = (blk - BB) * 16384;
        for (int i = tid; i < 16384; i += 256) {
            int idx = base + i;
            int a = idx >> 9, j = idx & 511;
            float v = W1[(size_t)a * (2 * DD) + DD + j];
            __half h = __float2half_rn(v);
            g_whi[idx] = h;
            g_wlo[idx] = __float2half_rn(v - __half2float(h));
        }
    }
}

// ============ GEMM (fp16: src rounded, W 2-term split) + fused score epilogue ============
__global__ void __launch_bounds__(256, 2)
gemm_k(const float* __restrict__ src, float* __restrict__ scores, const float* __restrict__ W2) {
    extern __shared__ char sm[];
    uint32_t smb = smem_u32(sm);
    int tid = threadIdx.x, lid = tid & 31, wid = tid >> 5;
    int wm = wid & 3, wn = wid >> 2;      // 4 m-warps x 2 n-warps
    int b = blockIdx.y;
    int s0 = blockIdx.x * 128;

    float* u_sm  = (float*)(sm + U_OFF);
    float* w2_sm = (float*)(sm + W2_OFF);
    for (int i = tid; i < DD; i += 256) { u_sm[i] = g_u[b * DD + i]; w2_sm[i] = W2[i]; }
    __syncthreads();

    const float* srcb = src + (size_t)b * DD;   // src[s][b][d]; s-stride = BB*DD

    float sc[4] = {0.f, 0.f, 0.f, 0.f};

    for (int nt = 0; nt < 4; nt++) {
        float acc[2][8][4];
        #pragma unroll
        for (int i = 0; i < 2; i++)
            #pragma unroll
            for (int j = 0; j < 8; j++)
                #pragma unroll
                for (int k = 0; k < 4; k++) acc[i][j][k] = 0.f;

        const __half* wh = g_whi + (size_t)(nt * 128) * DD;
        const __half* wl = g_wlo + (size_t)(nt * 128) * DD;

        float4 av[4];
        // ---- prologue: chunk 0 into stage 0 ----
        {
            #pragma unroll
            for (int t = 0; t < 4; t++) {
                int q = tid + 256 * t, r = q >> 3, s4 = q & 7;
                av[t] = *(const float4*)(srcb + (size_t)(s0 + r) * (BB * DD) + s4 * 4);
            }
            uint32_t sb = smb + TILE_OFF;
            #pragma unroll
            for (int t = 0; t < 2; t++) {
                int q = tid + 256 * t, n = q >> 2, sg = q & 3;
                uint32_t d0 = sb + (uint32_t)(n * ROWB + sg * 16);
                cp16(d0 + BHI_O, wh + (size_t)n * DD + sg * 8);
                cp16(d0 + BLO_O, wl + (size_t)n * DD + sg * 8);
            }
            asm volatile("cp.async.commit_group;" ::: "memory");
            char* sp = sm + TILE_OFF;
            #pragma unroll
            for (int t = 0; t < 4; t++) {
                int q = tid + 256 * t, r = q >> 3, s4 = q & 7;
                float4 v = av[t];
                uint32_t off = (uint32_t)(r * ROWB + s4 * 8);
                *(uint2*)(sp + A_O + off) = make_uint2(
                    packh2(__float2half_rn(v.x), __float2half_rn(v.y)),
                    packh2(__float2half_rn(v.z), __float2half_rn(v.w)));
            }
        }

        for (int ck = 0; ck < 16; ck++) {
            int st = ck & 1;
            uint32_t sbase = smb + TILE_OFF + st * ST_SZ;

            if (ck < 15) {  // prefetch next A chunk into regs
                int k0 = (ck + 1) * 32;
                #pragma unroll
                for (int t = 0; t < 4; t++) {
                    int q = tid + 256 * t, r = q >> 3, s4 = q & 7;
                    av[t] = *(const float4*)(srcb + (size_t)(s0 + r) * (BB * DD) + k0 + s4 * 4);
                }
            }
            asm volatile("cp.async.wait_group 0;" ::: "memory");
            __syncthreads();
            if (ck < 15) {  // issue next B cp.async into other stage
                int k0 = (ck + 1) * 32;
                uint32_t sb = smb + TILE_OFF + (st ^ 1) * ST_SZ;
                #pragma unroll
                for (int t = 0; t < 2; t++) {
                    int q = tid + 256 * t, n = q >> 2, sg = q & 3;
                    uint32_t d0 = sb + (uint32_t)(n * ROWB + sg * 16);
                    cp16(d0 + BHI_O, wh + (size_t)n * DD + k0 + sg * 8);
                    cp16(d0 + BLO_O, wl + (size_t)n * DD + k0 + sg * 8);
                }
                asm volatile("cp.async.commit_group;" ::: "memory");
            }

            // ---- mma on current stage: acc += A*(Whi + Wlo) ----
            #pragma unroll
            for (int ks = 0; ks < 2; ks++) {
                uint32_t af[2][4];
                uint32_t aoff = (uint32_t)((wm * 32 + (lid & 15)) * ROWB) + ks * 32 + (lid >> 4) * 16;
                LDSM4(af[0], sbase + A_O + aoff);
                LDSM4(af[1], sbase + A_O + aoff + 16 * ROWB);
                #pragma unroll
                for (int p = 0; p < 4; p++) {
                    uint32_t bh[4], bl[4];
                    uint32_t boff = (uint32_t)((wn * 64 + p * 16 + ((lid >> 4) << 3) + (lid & 7)) * ROWB)
                                  + ks * 32 + ((lid >> 3) & 1) * 16;
                    LDSM4(bh, sbase + BHI_O + boff);
                    LDSM4(bl, sbase + BLO_O + boff);
                    #pragma unroll
                    for (int mt = 0; mt < 2; mt++) {
                        MMA(acc[mt][2 * p],     af[mt], bh);
                        MMA(acc[mt][2 * p + 1], af[mt], bh + 2);
                        MMA(acc[mt][2 * p],     af[mt], bl);
                        MMA(acc[mt][2 * p + 1], af[mt], bl + 2);
                    }
                }
            }

            if (ck < 15) {  // store prefetched A into other stage
                char* sp = sm + TILE_OFF + (st ^ 1) * ST_SZ;
                #pragma unroll
                for (int t = 0; t < 4; t++) {
                    int q = tid + 256 * t, r = q >> 3, s4 = q & 7;
                    float4 v = av[t];
                    uint32_t off = (uint32_t)(r * ROWB + s4 * 8);
                    *(uint2*)(sp + A_O + off) = make_uint2(
                        packh2(__float2half_rn(v.x), __float2half_rn(v.y)),
                        packh2(__float2half_rn(v.z), __float2half_rn(v.w)));
                }
            }
        }

        // ---- epilogue for this n-tile: sc += sum_a W2[a]*tanh(acc + u[a]) ----
        {
            int tq = lid & 3;
            float part[4] = {0.f, 0.f, 0.f, 0.f};
            #pragma unroll
            for (int j = 0; j < 8; j++) {
                int a = nt * 128 + wn * 64 + j * 8 + tq * 2;
                float u0 = u_sm[a], u1 = u_sm[a + 1];
                float w0 = w2_sm[a], w1 = w2_sm[a + 1];
                #pragma unroll
                for (int mt = 0; mt < 2; mt++) {
                    part[mt * 2 + 0] += w0 * tanh_f(acc[mt][j][0] + u0)
                                      + w1 * tanh_f(acc[mt][j][1] + u1);
                    part[mt * 2 + 1] += w0 * tanh_f(acc[mt][j][2] + u0)
                                      + w1 * tanh_f(acc[mt][j][3] + u1);
                }
            }
            #pragma unroll
            for (int i = 0; i < 4; i++) {
                part[i] += __shfl_xor_sync(0xffffffffu, part[i], 1);
                part[i] += __shfl_xor_sync(0xffffffffu, part[i], 2);
                sc[i] += part[i];
            }
        }
    }

    // ---- cross-warp (n-warp) reduction + store scores ----
    float* red = (float*)(sm + RED_OFF);
    __syncthreads();
    if ((lid & 3) == 0) {
        int g = lid >> 2;
        #pragma unroll
        for (int mt = 0; mt < 2; mt++) {
            red[wn * 128 + wm * 32 + mt * 16 + g]     = sc[mt * 2 + 0];
            red[wn * 128 + wm * 32 + mt * 16 + 8 + g] = sc[mt * 2 + 1];
        }
    }
    __syncthreads();
    if (tid < 128)
        scores[(size_t)(s0 + tid) * BB + b] = red[tid] + red[128 + tid];
}

// ==================== softmax over S (in place) ====================
__global__ void softmax_k(float* __restrict__ attn, const unsigned char* __restrict__ mask) {
    __shared__ float red[256];
    int b = blockIdx.x, tid = threadIdx.x;
    float v[8];
    float mx = -1e30f;
    #pragma unroll
    for (int i = 0; i < 8; i++) {
        int s = tid + i * 256;
        float x = attn[(size_t)s * BB + b];
        if (mask[(size_t)s * BB + b]) x = -1e30f;
        v[i] = x;
        mx = fmaxf(mx, x);
    }
    red[tid] = mx; __syncthreads();
    for (int o = 128; o > 0; o >>= 1) { if (tid < o) red[tid] = fmaxf(red[tid], red[tid + o]); __syncthreads(); }
    mx = red[0]; __syncthreads();
    float sum = 0.f;
    #pragma unroll
    for (int i = 0; i < 8; i++) { v[i] = __expf(v[i] - mx); sum += v[i]; }
    red[tid] = sum; __syncthreads();
    for (int o = 128; o > 0; o >>= 1) { if (tid < o) red[tid] += red[tid + o]; __syncthreads(); }
    float inv = __fdividef(1.f, red[0]);
    #pragma unroll
    for (int i = 0; i < 8; i++) attn[(size_t)(tid + i * 256) * BB + b] = v[i] * inv;
}

// ==================== ctx = sum_s attn[s,b] * src[s,b,:] ====================
__global__ void ctx_k(const float* __restrict__ src, const float* __restrict__ attn) {
    int b = blockIdx.x, dch = blockIdx.y, sch = blockIdx.z, tid = threadIdx.x;
    int d = dch * 256 + tid;
    const float* sp = src + (size_t)b * DD + d;
    int s0 = sch * 256;
    float a0 = 0.f, a1 = 0.f, a2 = 0.f, a3 = 0.f;
    for (int s = s0; s < s0 + 256; s += 4) {
        a0 += attn[(size_t)(s + 0) * BB + b] * sp[(size_t)(s + 0) * (BB * DD)];
        a1 += attn[(size_t)(s + 1) * BB + b] * sp[(size_t)(s + 1) * (BB * DD)];
        a2 += attn[(size_t)(s + 2) * BB + b] * sp[(size_t)(s + 2) * (BB * DD)];
        a3 += attn[(size_t)(s + 3) * BB + b] * sp[(size_t)(s + 3) * (BB * DD)];
    }
    g_part[((sch * BB + b) << 9) + d] = (a0 + a1) + (a2 + a3);
}

__global__ void red_k(float* __restrict__ out) {
    int i = blockIdx.x * 512 + threadIdx.x;
    float s = 0.f;
    #pragma unroll
    for (int j = 0; j < 8; j++) s += g_part[j * (BB * DD) + i];
    out[i] = s;
}

// ==================== launch ====================
extern "C" void kernel_launch(void* const* d_in, const int* in_sizes, int n_in,
                              void* d_out, int out_size) {
    (void)in_sizes; (void)n_in; (void)out_size;
    const float* input = (const float*)d_in[0];
    const float* src = (const float*)d_in[1];
    const unsigned char* mask = (const unsigned char*)d_in[2];
    const float* W1 = (const float*)d_in[3];
    const float* b1 = (const float*)d_in[4];
    const float* W2 = (const float*)d_in[5];
    float* out = (float*)d_out;          // [ctx: 64*512][attn: 2048*64]
    float* attn = out + BB * DD;

    cudaFuncSetAttribute(gemm_k, cudaFuncAttributeMaxDynamicSharedMemorySize, DYN_SMEM);

    prep_k<<<80, 256>>>(input, W1, b1);
    gemm_k<<<dim3(16, BB), 256, DYN_SMEM>>>(src, attn, W2);
    softmax_k<<<BB, 256>>>(attn, mask);
    ctx_k<<<dim3(BB, 2, 8), 256>>>(src, attn);
    red_k<<<BB, 512>>>(out);
}

// round 7
// speedup vs baseline: 1.7867x; 1.7867x over previous
#include <cuda_runtime.h>
#include <cuda_fp16.h>
#include <cstdint>

#define SS 2048
#define BB 64
#define DD 512

// ---------------- device scratch (static; no runtime allocs) ----------------
__device__ float g_u[BB * DD];                      // u[b,a] = input.W1x + b1
__device__ __align__(16) __half g_whi[DD * DD];     // W1_src (fp16 rne), K-major [a][d]
__device__ float g_part[8 * BB * DD];               // ctx partials (8 s-slices)

// ---------------- helpers ----------------
__device__ __forceinline__ uint32_t smem_u32(const void* p) {
    uint32_t a;
    asm("{ .reg .u64 t; cvta.to.shared.u64 t, %1; cvt.u32.u64 %0, t; }" : "=r"(a) : "l"(p));
    return a;
}
__device__ __forceinline__ uint32_t packh2(__half a, __half b) {
    __half2 h = __halves2half2(a, b);
    return *reinterpret_cast<uint32_t*>(&h);
}
__device__ __forceinline__ void cp16(uint32_t dst, const void* src) {
    asm volatile("cp.async.cg.shared.global [%0], [%1], 16;" :: "r"(dst), "l"(src) : "memory");
}
__device__ __forceinline__ float tanh_f(float x) {
    float e = __expf(2.f * x);
    return 1.f - __fdividef(2.f, e + 1.f);
}

#define LDSM4(r, addr) \
    asm volatile("ldmatrix.sync.aligned.m8n8.x4.shared.b16 {%0,%1,%2,%3}, [%4];" \
        : "=r"((r)[0]), "=r"((r)[1]), "=r"((r)[2]), "=r"((r)[3]) : "r"(addr))

#define MMA(d, a, b) \
    asm volatile("mma.sync.aligned.m16n8k16.row.col.f32.f16.f16.f32 " \
        "{%0,%1,%2,%3}, {%4,%5,%6,%7}, {%8,%9}, {%0,%1,%2,%3};" \
        : "+f"((d)[0]), "+f"((d)[1]), "+f"((d)[2]), "+f"((d)[3]) \
        : "r"((a)[0]), "r"((a)[1]), "r"((a)[2]), "r"((a)[3]), "r"((b)[0]), "r"((b)[1]))

// ---------------- smem layout for gemm_k ----------------
#define U_OFF    0
#define W2_OFF   2048
#define RED_OFF  4096
#define A_O      5120
#define A_ROWB   1040            // 512 fp16 = 1024B + 16B pad (row stride = 4 banks -> LDSM clean)
#define A_SZ     (128 * A_ROWB)  // 133120
#define B_O      (A_O + A_SZ)    // 138240
#define ROWB     80              // B stage row stride: 64B data + 16B pad
#define BST_SZ   (128 * ROWB)    // 10240 per stage
#define NSTAGE   4
#define DYN_SMEM (B_O + NSTAGE * BST_SZ)   // 179200

// ==================== prep: u[b,a] ====================
__global__ void prep_u_k(const float* __restrict__ input, const float* __restrict__ W1,
                         const float* __restrict__ b1) {
    __shared__ float inp[DD];
    int blk = blockIdx.x, tid = threadIdx.x;
    inp[tid] = input[blk * DD + tid];
    inp[tid + 256] = input[blk * DD + tid + 256];
    __syncthreads();
    for (int a = tid; a < DD; a += 256) {
        const float* w = W1 + (size_t)a * (2 * DD);
        float acc = b1[a];
        #pragma unroll 8
        for (int d = 0; d < DD; d++) acc += inp[d] * w[d];
        g_u[blk * DD + a] = acc;
    }
}

// ==================== prep: W fp16 round ====================
__global__ void prep_w_k(const float* __restrict__ W1) {
    int base = blockIdx.x * 16384, tid = threadIdx.x;
    for (int i = tid; i < 16384; i += 256) {
        int idx = base + i;
        int a = idx >> 9, j = idx & 511;
        g_whi[idx] = __float2half_rn(W1[(size_t)a * (2 * DD) + DD + j]);
    }
}

__global__ void dummy_k() {}

// ============ GEMM (fp16 single-term) + fused score epilogue ============
__global__ void __launch_bounds__(256, 1)
gemm_k(const float* __restrict__ src, float* __restrict__ scores, const float* __restrict__ W2) {
    extern __shared__ char sm[];
    uint32_t smb = smem_u32(sm);
    int tid = threadIdx.x, lid = tid & 31, wid = tid >> 5;
    int wm = wid & 3, wn = wid >> 2;      // 4 m-warps x 2 n-warps
    int b = blockIdx.y;
    int s0 = blockIdx.x * 128;

    float* u_sm  = (float*)(sm + U_OFF);
    float* w2_sm = (float*)(sm + W2_OFF);
    for (int i = tid; i < DD; i += 256) { u_sm[i] = g_u[b * DD + i]; w2_sm[i] = W2[i]; }

    const float* srcb = src + (size_t)b * DD;   // src[s][b][d]; s-stride = BB*DD

    // ---- load + convert entire A tile (128 x 512 fp32 -> fp16) into smem, once ----
    {
        const int c4 = tid & 127;             // fixed float4-column per thread
        const int rb = tid >> 7;              // 0 or 1
        #pragma unroll 1
        for (int t8 = 0; t8 < 8; t8++) {
            float4 v[8];
            #pragma unroll
            for (int j = 0; j < 8; j++) {
                int r = rb + 2 * (t8 * 8 + j);
                v[j] = *(const float4*)(srcb + (size_t)(s0 + r) * (BB * DD) + c4 * 4);
            }
            #pragma unroll
            for (int j = 0; j < 8; j++) {
                int r = rb + 2 * (t8 * 8 + j);
                *(uint2*)(sm + A_O + r * A_ROWB + c4 * 8) = make_uint2(
                    packh2(__float2half_rn(v[j].x), __float2half_rn(v[j].y)),
                    packh2(__float2half_rn(v[j].z), __float2half_rn(v[j].w)));
            }
        }
    }

    // ---- B pipeline prologue: stages 0..2 ----
    #pragma unroll
    for (int f = 0; f < NSTAGE - 1; f++) {
        int fnt = f >> 4, fck = f & 15;
        const __half* wsrc = g_whi + (size_t)(fnt * 128) * DD + fck * 32;
        uint32_t sb = smb + B_O + (f & (NSTAGE - 1)) * BST_SZ;
        #pragma unroll
        for (int t = 0; t < 2; t++) {
            int q = tid + 256 * t, n = q >> 2, sg = q & 3;
            cp16(sb + (uint32_t)(n * ROWB + sg * 16), wsrc + (size_t)n * DD + sg * 8);
        }
        asm volatile("cp.async.commit_group;" ::: "memory");
    }
    __syncthreads();   // A tile + u/w2 visible

    float sc[4] = {0.f, 0.f, 0.f, 0.f};
    float acc[2][8][4];
    #pragma unroll
    for (int i = 0; i < 2; i++)
        #pragma unroll
        for (int j = 0; j < 8; j++)
            #pragma unroll
            for (int k = 0; k < 4; k++) acc[i][j][k] = 0.f;

    for (int idx = 0; idx < 64; idx++) {
        int nt = idx >> 4, ck = idx & 15;
        uint32_t sbase = smb + B_O + (idx & (NSTAGE - 1)) * BST_SZ;

        asm volatile("cp.async.wait_group %0;" :: "n"(NSTAGE - 2) : "memory");
        __syncthreads();

        // prefetch stage idx+3 (empty commit keeps group accounting exact at tail)
        {
            int f = idx + NSTAGE - 1;
            if (f < 64) {
                int fnt = f >> 4, fck = f & 15;
                const __half* wsrc = g_whi + (size_t)(fnt * 128) * DD + fck * 32;
                uint32_t sb = smb + B_O + (f & (NSTAGE - 1)) * BST_SZ;
                #pragma unroll
                for (int t = 0; t < 2; t++) {
                    int q = tid + 256 * t, n = q >> 2, sg = q & 3;
                    cp16(sb + (uint32_t)(n * ROWB + sg * 16), wsrc + (size_t)n * DD + sg * 8);
                }
            }
            asm volatile("cp.async.commit_group;" ::: "memory");
        }

        // ---- MMA: A from persistent smem, B from ring stage ----
        #pragma unroll
        for (int ks = 0; ks < 2; ks++) {
            uint32_t af[2][4];
            uint32_t aoff = smb + A_O
                          + (uint32_t)((wm * 32 + (lid & 15)) * A_ROWB)
                          + (uint32_t)((ck * 32 + ks * 16 + (lid >> 4) * 8) * 2);
            LDSM4(af[0], aoff);
            LDSM4(af[1], aoff + 16 * A_ROWB);
            #pragma unroll
            for (int p = 0; p < 4; p++) {
                uint32_t bh[4];
                uint32_t boff = sbase
                              + (uint32_t)((wn * 64 + p * 16 + ((lid >> 4) << 3) + (lid & 7)) * ROWB)
                              + (uint32_t)(ks * 32 + ((lid >> 3) & 1) * 16);
                LDSM4(bh, boff);
                #pragma unroll
                for (int mt = 0; mt < 2; mt++) {
                    MMA(acc[mt][2 * p],     af[mt], bh);
                    MMA(acc[mt][2 * p + 1], af[mt], bh + 2);
                }
            }
        }

        // ---- nt boundary: fold acc into score partials, reset ----
        if (ck == 15) {
            int tq = lid & 3;
            float part[4] = {0.f, 0.f, 0.f, 0.f};
            #pragma unroll
            for (int j = 0; j < 8; j++) {
                int a = nt * 128 + wn * 64 + j * 8 + tq * 2;
                float u0 = u_sm[a], u1 = u_sm[a + 1];
                float w0 = w2_sm[a], w1 = w2_sm[a + 1];
                #pragma unroll
                for (int mt = 0; mt < 2; mt++) {
                    part[mt * 2 + 0] += w0 * tanh_f(acc[mt][j][0] + u0)
                                      + w1 * tanh_f(acc[mt][j][1] + u1);
                    part[mt * 2 + 1] += w0 * tanh_f(acc[mt][j][2] + u0)
                                      + w1 * tanh_f(acc[mt][j][3] + u1);
                }
            }
            #pragma unroll
            for (int i = 0; i < 4; i++) {
                part[i] += __shfl_xor_sync(0xffffffffu, part[i], 1);
                part[i] += __shfl_xor_sync(0xffffffffu, part[i], 2);
                sc[i] += part[i];
            }
            #pragma unroll
            for (int i = 0; i < 2; i++)
                #pragma unroll
                for (int j = 0; j < 8; j++)
                    #pragma unroll
                    for (int k = 0; k < 4; k++) acc[i][j][k] = 0.f;
        }
    }

    // ---- cross-warp (n-warp) reduction + store scores ----
    float* red = (float*)(sm + RED_OFF);
    __syncthreads();
    if ((lid & 3) == 0) {
        int g = lid >> 2;
        #pragma unroll
        for (int mt = 0; mt < 2; mt++) {
            red[wn * 128 + wm * 32 + mt * 16 + g]     = sc[mt * 2 + 0];
            red[wn * 128 + wm * 32 + mt * 16 + 8 + g] = sc[mt * 2 + 1];
        }
    }
    __syncthreads();
    if (tid < 128)
        scores[(size_t)(s0 + tid) * BB + b] = red[tid] + red[128 + tid];
}

// ==================== softmax over S (in place) ====================
__global__ void softmax_k(float* __restrict__ attn, const unsigned char* __restrict__ mask) {
    __shared__ float red[256];
    int b = blockIdx.x, tid = threadIdx.x;
    float v[8];
    float mx = -1e30f;
    #pragma unroll
    for (int i = 0; i < 8; i++) {
        int s = tid + i * 256;
        float x = attn[(size_t)s * BB + b];
        if (mask[(size_t)s * BB + b]) x = -1e30f;
        v[i] = x;
        mx = fmaxf(mx, x);
    }
    red[tid] = mx; __syncthreads();
    for (int o = 128; o > 0; o >>= 1) { if (tid < o) red[tid] = fmaxf(red[tid], red[tid + o]); __syncthreads(); }
    mx = red[0]; __syncthreads();
    float sum = 0.f;
    #pragma unroll
    for (int i = 0; i < 8; i++) { v[i] = __expf(v[i] - mx); sum += v[i]; }
    red[tid] = sum; __syncthreads();
    for (int o = 128; o > 0; o >>= 1) { if (tid < o) red[tid] += red[tid + o]; __syncthreads(); }
    float inv = __fdividef(1.f, red[0]);
    #pragma unroll
    for (int i = 0; i < 8; i++) attn[(size_t)(tid + i * 256) * BB + b] = v[i] * inv;
}

// ==================== ctx = sum_s attn[s,b] * src[s,b,:] ====================
__global__ void ctx_k(const float* __restrict__ src, const float* __restrict__ attn) {
    int b = blockIdx.x, dch = blockIdx.y, sch = blockIdx.z, tid = threadIdx.x;
    int d = dch * 256 + tid;
    const float* sp = src + (size_t)b * DD + d;
    int s0 = sch * 256;
    float a[8] = {0.f, 0.f, 0.f, 0.f, 0.f, 0.f, 0.f, 0.f};
    #pragma unroll 4
    for (int s = s0; s < s0 + 256; s += 8) {
        #pragma unroll
        for (int j = 0; j < 8; j++)
            a[j] += attn[(size_t)(s + j) * BB + b] * sp[(size_t)(s + j) * (BB * DD)];
    }
    float t = ((a[0] + a[1]) + (a[2] + a[3])) + ((a[4] + a[5]) + (a[6] + a[7]));
    g_part[((sch * BB + b) << 9) + d] = t;
}

__global__ void red_k(float* __restrict__ out) {
    int i = blockIdx.x * 512 + threadIdx.x;
    float s = 0.f;
    #pragma unroll
    for (int j = 0; j < 8; j++) s += g_part[j * (BB * DD) + i];
    out[i] = s;
}

// ==================== launch ====================
extern "C" void kernel_launch(void* const* d_in, const int* in_sizes, int n_in,
                              void* d_out, int out_size) {
    (void)in_sizes; (void)n_in; (void)out_size;
    const float* input = (const float*)d_in[0];
    const float* src = (const float*)d_in[1];
    const unsigned char* mask = (const unsigned char*)d_in[2];
    const float* W1 = (const float*)d_in[3];
    const float* b1 = (const float*)d_in[4];
    const float* W2 = (const float*)d_in[5];
    float* out = (float*)d_out;          // [ctx: 64*512][attn: 2048*64]
    float* attn = out + BB * DD;

    cudaFuncSetAttribute(gemm_k, cudaFuncAttributeMaxDynamicSharedMemorySize, DYN_SMEM);

    prep_u_k<<<BB, 256>>>(input, W1, b1);        // launch 1
    prep_w_k<<<16, 256>>>(W1);                   // launch 2
    dummy_k<<<1, 32>>>();                        // launch 3 (aligns ncu capture to gemm_k)
    gemm_k<<<dim3(16, BB), 256, DYN_SMEM>>>(src, attn, W2);   // launch 4
    softmax_k<<<BB, 256>>>(attn, mask);
    ctx_k<<<dim3(BB, 2, 8), 256>>>(src, attn);
    red_k<<<BB, 512>>>(out);
}

// round 10
// speedup vs baseline: 1.9255x; 1.0777x over previous
#include <cuda_runtime.h>
#include <cuda_fp16.h>
#include <cstdint>

#define SS 2048
#define BB 64
#define DD 512

// ---------------- device scratch (static; no runtime allocs) ----------------
__device__ float g_u[BB * DD];                      // u[b,a] = input.W1x + b1
__device__ __align__(16) __half g_whi[DD * DD];     // W1_src (fp16 rne), K-major [a][d]
__device__ float g_part[8 * BB * DD];               // ctx partials (8 s-slices)

// ---------------- helpers ----------------
__device__ __forceinline__ uint32_t smem_u32(const void* p) {
    uint32_t a;
    asm("{ .reg .u64 t; cvta.to.shared.u64 t, %1; cvt.u32.u64 %0, t; }" : "=r"(a) : "l"(p));
    return a;
}
__device__ __forceinline__ uint32_t packh2(__half a, __half b) {
    __half2 h = __halves2half2(a, b);
    return *reinterpret_cast<uint32_t*>(&h);
}
__device__ __forceinline__ void cp16(uint32_t dst, const void* src) {
    asm volatile("cp.async.cg.shared.global [%0], [%1], 16;" :: "r"(dst), "l"(src) : "memory");
}
__device__ __forceinline__ float tanh_f(float x) {
    float e = __expf(2.f * x);
    return 1.f - __fdividef(2.f, e + 1.f);
}

#define LDSM4(r, addr) \
    asm volatile("ldmatrix.sync.aligned.m8n8.x4.shared.b16 {%0,%1,%2,%3}, [%4];" \
        : "=r"((r)[0]), "=r"((r)[1]), "=r"((r)[2]), "=r"((r)[3]) : "r"(addr))

#define MMA(d, a, b) \
    asm volatile("mma.sync.aligned.m16n8k16.row.col.f32.f16.f16.f32 " \
        "{%0,%1,%2,%3}, {%4,%5,%6,%7}, {%8,%9}, {%0,%1,%2,%3};" \
        : "+f"((d)[0]), "+f"((d)[1]), "+f"((d)[2]), "+f"((d)[3]) \
        : "r"((a)[0]), "r"((a)[1]), "r"((a)[2]), "r"((a)[3]), "r"((b)[0]), "r"((b)[1]))

// ---------------- smem layout for gemm_k ----------------
#define U_OFF    0
#define W2_OFF   2048
#define RED_OFF  4096            // 4 planes x 128 f = 2048 B
#define A_O      6144
#define A_ROWB   1040            // 512 fp16 = 1024B + 16B pad -> conflict-free LDSM
#define A_SZ     (128 * A_ROWB)  // 133120
#define B_O      (A_O + A_SZ)    // 139264
#define ROWB     80              // B stage row stride: 64B data + 16B pad
#define BST_SZ   (128 * ROWB)    // 10240 per stage
#define NSTAGE   4
#define DYN_SMEM (B_O + NSTAGE * BST_SZ)   // 180224

// ==================== prep: u[b,a] ====================
__global__ void prep_u_k(const float* __restrict__ input, const float* __restrict__ W1,
                         const float* __restrict__ b1) {
    __shared__ float inp[DD];
    int blk = blockIdx.x, tid = threadIdx.x;
    inp[tid] = input[blk * DD + tid];
    inp[tid + 256] = input[blk * DD + tid + 256];
    __syncthreads();
    for (int a = tid; a < DD; a += 256) {
        const float* w = W1 + (size_t)a * (2 * DD);
        float acc = b1[a];
        #pragma unroll 8
        for (int d = 0; d < DD; d++) acc += inp[d] * w[d];
        g_u[blk * DD + a] = acc;
    }
}

// ==================== prep: W fp16 round ====================
__global__ void prep_w_k(const float* __restrict__ W1) {
    int base = blockIdx.x * 16384, tid = threadIdx.x;
    for (int i = tid; i < 16384; i += 256) {
        int idx = base + i;
        int a = idx >> 9, j = idx & 511;
        g_whi[idx] = __float2half_rn(W1[(size_t)a * (2 * DD) + DD + j]);
    }
}

__global__ void dummy_k() {}

// ============ GEMM (fp16 single-term, 16 warps 4x4) + fused score epilogue ============
__global__ void __launch_bounds__(512, 1)
gemm_k(const float* __restrict__ src, float* __restrict__ scores, const float* __restrict__ W2) {
    extern __shared__ char sm[];
    uint32_t smb = smem_u32(sm);
    int tid = threadIdx.x, lid = tid & 31, wid = tid >> 5;
    int wm = wid & 3, wn = wid >> 2;      // 4 m-warps (32 rows) x 4 n-warps (32 cols)
    int b = blockIdx.y;
    int s0 = blockIdx.x * 128;

    float* u_sm  = (float*)(sm + U_OFF);
    float* w2_sm = (float*)(sm + W2_OFF);
    for (int i = tid; i < DD; i += 512) { u_sm[i] = g_u[b * DD + i]; w2_sm[i] = W2[i]; }

    const float* srcb = src + (size_t)b * DD;   // src[s][b][d]; s-stride = BB*DD

    // ---- load + convert entire A tile (128 x 512 fp32 -> fp16) into smem, once ----
    {
        const int c4 = tid & 127;             // fixed float4-column per thread
        const int rb = tid >> 7;              // 0..3
        #pragma unroll 1
        for (int t8 = 0; t8 < 4; t8++) {
            float4 v[8];
            #pragma unroll
            for (int j = 0; j < 8; j++) {
                int r = rb + 4 * (t8 * 8 + j);
                v[j] = *(const float4*)(srcb + (size_t)(s0 + r) * (BB * DD) + c4 * 4);
            }
            #pragma unroll
            for (int j = 0; j < 8; j++) {
                int r = rb + 4 * (t8 * 8 + j);
                *(uint2*)(sm + A_O + r * A_ROWB + c4 * 8) = make_uint2(
                    packh2(__float2half_rn(v[j].x), __float2half_rn(v[j].y)),
                    packh2(__float2half_rn(v[j].z), __float2half_rn(v[j].w)));
            }
        }
    }

    // ---- B pipeline prologue: stages 0..2 ----
    #pragma unroll
    for (int f = 0; f < NSTAGE - 1; f++) {
        int fnt = f >> 4, fck = f & 15;
        const __half* wsrc = g_whi + (size_t)(fnt * 128) * DD + fck * 32;
        uint32_t sb = smb + B_O + (f & (NSTAGE - 1)) * BST_SZ;
        int n = tid >> 2, sg = tid & 3;
        cp16(sb + (uint32_t)(n * ROWB + sg * 16), wsrc + (size_t)n * DD + sg * 8);
        asm volatile("cp.async.commit_group;" ::: "memory");
    }
    __syncthreads();   // A tile + u/w2 visible

    float sc[4] = {0.f, 0.f, 0.f, 0.f};
    float acc[2][4][4];
    #pragma unroll
    for (int i = 0; i < 2; i++)
        #pragma unroll
        for (int j = 0; j < 4; j++)
            #pragma unroll
            for (int k = 0; k < 4; k++) acc[i][j][k] = 0.f;

    for (int idx = 0; idx < 64; idx++) {
        int nt = idx >> 4, ck = idx & 15;
        uint32_t sbase = smb + B_O + (idx & (NSTAGE - 1)) * BST_SZ;

        asm volatile("cp.async.wait_group %0;" :: "n"(NSTAGE - 2) : "memory");
        __syncthreads();

        // prefetch stage idx+3 (always-commit keeps group accounting exact at tail)
        {
            int f = idx + NSTAGE - 1;
            if (f < 64) {
                int fnt = f >> 4, fck = f & 15;
                const __half* wsrc = g_whi + (size_t)(fnt * 128) * DD + fck * 32;
                uint32_t sb = smb + B_O + (f & (NSTAGE - 1)) * BST_SZ;
                int n = tid >> 2, sg = tid & 3;
                cp16(sb + (uint32_t)(n * ROWB + sg * 16), wsrc + (size_t)n * DD + sg * 8);
            }
            asm volatile("cp.async.commit_group;" ::: "memory");
        }

        // ---- MMA: A from persistent smem, B from ring stage ----
        #pragma unroll
        for (int ks = 0; ks < 2; ks++) {
            uint32_t af[2][4];
            uint32_t aoff = smb + A_O
                          + (uint32_t)((wm * 32 + (lid & 15)) * A_ROWB)
                          + (uint32_t)((ck * 32 + ks * 16 + (lid >> 4) * 8) * 2);
            LDSM4(af[0], aoff);
            LDSM4(af[1], aoff + 16 * A_ROWB);
            #pragma unroll
            for (int p = 0; p < 2; p++) {
                uint32_t bh[4];
                uint32_t boff = sbase
                              + (uint32_t)((wn * 32 + p * 16 + ((lid >> 4) << 3) + (lid & 7)) * ROWB)
                              + (uint32_t)(ks * 32 + ((lid >> 3) & 1) * 16);
                LDSM4(bh, boff);
                #pragma unroll
                for (int mt = 0; mt < 2; mt++) {
                    MMA(acc[mt][2 * p],     af[mt], bh);
                    MMA(acc[mt][2 * p + 1], af[mt], bh + 2);
                }
            }
        }

        // ---- nt boundary: fold acc into score partials, reset ----
        if (ck == 15) {
            int tq = lid & 3;
            float part[4] = {0.f, 0.f, 0.f, 0.f};
            #pragma unroll
            for (int j = 0; j < 4; j++) {
                int a = nt * 128 + wn * 32 + j * 8 + tq * 2;
                float u0 = u_sm[a], u1 = u_sm[a + 1];
                float w0 = w2_sm[a], w1 = w2_sm[a + 1];
                #pragma unroll
                for (int mt = 0; mt < 2; mt++) {
                    part[mt * 2 + 0] += w0 * tanh_f(acc[mt][j][0] + u0)
                                      + w1 * tanh_f(acc[mt][j][1] + u1);
                    part[mt * 2 + 1] += w0 * tanh_f(acc[mt][j][2] + u0)
                                      + w1 * tanh_f(acc[mt][j][3] + u1);
                }
            }
            #pragma unroll
            for (int i = 0; i < 4; i++) {
                part[i] += __shfl_xor_sync(0xffffffffu, part[i], 1);
                part[i] += __shfl_xor_sync(0xffffffffu, part[i], 2);
                sc[i] += part[i];
            }
            #pragma unroll
            for (int i = 0; i < 2; i++)
                #pragma unroll
                for (int j = 0; j < 4; j++)
                    #pragma unroll
                    for (int k = 0; k < 4; k++) acc[i][j][k] = 0.f;
        }
    }

    // ---- cross-warp (4 n-warp planes) reduction + store scores ----
    float* red = (float*)(sm + RED_OFF);
    __syncthreads();
    if ((lid & 3) == 0) {
        int g = lid >> 2;
        #pragma unroll
        for (int mt = 0; mt < 2; mt++) {
            red[wn * 128 + wm * 32 + mt * 16 + g]     = sc[mt * 2 + 0];
            red[wn * 128 + wm * 32 + mt * 16 + 8 + g] = sc[mt * 2 + 1];
        }
    }
    __syncthreads();
    if (tid < 128)
        scores[(size_t)(s0 + tid) * BB + b] =
            (red[tid] + red[128 + tid]) + (red[256 + tid] + red[384 + tid]);
}

// ==================== softmax over S (in place) ====================
__global__ void softmax_k(float* __restrict__ attn, const unsigned char* __restrict__ mask) {
    __shared__ float red[256];
    int b = blockIdx.x, tid = threadIdx.x;
    float v[8];
    float mx = -1e30f;
    #pragma unroll
    for (int i = 0; i < 8; i++) {
        int s = tid + i * 256;
        float x = attn[(size_t)s * BB + b];
        if (mask[(size_t)s * BB + b]) x = -1e30f;
        v[i] = x;
        mx = fmaxf(mx, x);
    }
    red[tid] = mx; __syncthreads();
    for (int o = 128; o > 0; o >>= 1) { if (tid < o) red[tid] = fmaxf(red[tid], red[tid + o]); __syncthreads(); }
    mx = red[0]; __syncthreads();
    float sum = 0.f;
    #pragma unroll
    for (int i = 0; i < 8; i++) { v[i] = __expf(v[i] - mx); sum += v[i]; }
    red[tid] = sum; __syncthreads();
    for (int o = 128; o > 0; o >>= 1) { if (tid < o) red[tid] += red[tid + o]; __syncthreads(); }
    float inv = __fdividef(1.f, red[0]);
    #pragma unroll
    for (int i = 0; i < 8; i++) attn[(size_t)(tid + i * 256) * BB + b] = v[i] * inv;
}

// ==================== ctx = sum_s attn[s,b] * src[s,b,:] ====================
__global__ void ctx_k(const float* __restrict__ src, const float* __restrict__ attn) {
    int b = blockIdx.x, dch = blockIdx.y, sch = blockIdx.z, tid = threadIdx.x;
    int d = dch * 256 + tid;
    const float* sp = src + (size_t)b * DD + d;
    int s0 = sch * 256;
    float a[8] = {0.f, 0.f, 0.f, 0.f, 0.f, 0.f, 0.f, 0.f};
    #pragma unroll 4
    for (int s = s0; s < s0 + 256; s += 8) {
        #pragma unroll
        for (int j = 0; j < 8; j++)
            a[j] += attn[(size_t)(s + j) * BB + b] * sp[(size_t)(s + j) * (BB * DD)];
    }
    float t = ((a[0] + a[1]) + (a[2] + a[3])) + ((a[4] + a[5]) + (a[6] + a[7]));
    g_part[((sch * BB + b) << 9) + d] = t;
}

__global__ void red_k(float* __restrict__ out) {
    int i = blockIdx.x * 512 + threadIdx.x;
    float s = 0.f;
    #pragma unroll
    for (int j = 0; j < 8; j++) s += g_part[j * (BB * DD) + i];
    out[i] = s;
}

// ==================== launch ====================
extern "C" void kernel_launch(void* const* d_in, const int* in_sizes, int n_in,
                              void* d_out, int out_size) {
    (void)in_sizes; (void)n_in; (void)out_size;
    const float* input = (const float*)d_in[0];
    const float* src = (const float*)d_in[1];
    const unsigned char* mask = (const unsigned char*)d_in[2];
    const float* W1 = (const float*)d_in[3];
    const float* b1 = (const float*)d_in[4];
    const float* W2 = (const float*)d_in[5];
    float* out = (float*)d_out;          // [ctx: 64*512][attn: 2048*64]
    float* attn = out + BB * DD;

    cudaFuncSetAttribute(gemm_k, cudaFuncAttributeMaxDynamicSharedMemorySize, DYN_SMEM);

    prep_u_k<<<BB, 256>>>(input, W1, b1);        // launch 1
    prep_w_k<<<16, 256>>>(W1);                   // launch 2
    dummy_k<<<1, 32>>>();                        // launch 3
    gemm_k<<<dim3(16, BB), 512, DYN_SMEM>>>(src, attn, W2);   // launch 4
    softmax_k<<<BB, 256>>>(attn, mask);
    ctx_k<<<dim3(BB, 2, 8), 256>>>(src, attn);
    red_k<<<BB, 512>>>(out);
}

// round 11
// speedup vs baseline: 2.1492x; 1.1162x over previous
#include <cuda_runtime.h>
#include <cuda_fp16.h>
#include <cstdint>

#define SS 2048
#define BB 64
#define DD 512

// ---------------- device scratch (static; no runtime allocs) ----------------
__device__ float g_u[BB * DD];                      // u[b,a] = input.W1x + b1
__device__ __align__(16) __half g_whi[DD * DD];     // W1_src (fp16 rne), K-major [a][d]
__device__ float g_part[8 * BB * DD];               // ctx partials (8 s-slices)

// ---------------- helpers ----------------
__device__ __forceinline__ uint32_t smem_u32(const void* p) {
    uint32_t a;
    asm("{ .reg .u64 t; cvta.to.shared.u64 t, %1; cvt.u32.u64 %0, t; }" : "=r"(a) : "l"(p));
    return a;
}
__device__ __forceinline__ uint32_t packh2(__half a, __half b) {
    __half2 h = __halves2half2(a, b);
    return *reinterpret_cast<uint32_t*>(&h);
}
__device__ __forceinline__ void cp16(uint32_t dst, const void* src) {
    asm volatile("cp.async.cg.shared.global [%0], [%1], 16;" :: "r"(dst), "l"(src) : "memory");
}
__device__ __forceinline__ float tanh_f(float x) {
    float e = __expf(2.f * x);
    return 1.f - __fdividef(2.f, e + 1.f);
}

#define LDSM4(r, addr) \
    asm volatile("ldmatrix.sync.aligned.m8n8.x4.shared.b16 {%0,%1,%2,%3}, [%4];" \
        : "=r"((r)[0]), "=r"((r)[1]), "=r"((r)[2]), "=r"((r)[3]) : "r"(addr))

#define MMA(d, a, b) \
    asm volatile("mma.sync.aligned.m16n8k16.row.col.f32.f16.f16.f32 " \
        "{%0,%1,%2,%3}, {%4,%5,%6,%7}, {%8,%9}, {%0,%1,%2,%3};" \
        : "+f"((d)[0]), "+f"((d)[1]), "+f"((d)[2]), "+f"((d)[3]) \
        : "r"((a)[0]), "r"((a)[1]), "r"((a)[2]), "r"((a)[3]), "r"((b)[0]), "r"((b)[1]))

#define BARG(id) asm volatile("bar.sync %0, 128;" :: "r"(id) : "memory")

// ---------------- smem layout for gemm_k ----------------
#define U_OFF    0
#define W2_OFF   2048
#define RED_OFF  4096            // 4 planes x 128 f = 2048 B
#define A_O      6144
#define A_ROWB   1040            // 512 fp16 = 1024B + 16B pad -> conflict-free LDSM
#define A_SZ     (128 * A_ROWB)  // 133120
#define B_O      (A_O + A_SZ)    // 139264
#define ROWB2    144             // B row: 128B data (k64 fp16) + 16B pad
#define GST      (32 * ROWB2)    // 4608 per group per stage
#define STG_ALL  (4 * GST)       // 18432 per stage (4 groups)
#define NSTAGE   3
#define DYN_SMEM (B_O + NSTAGE * STG_ALL)   // 194560

// ==================== prep: u[b,a] ====================
__global__ void prep_u_k(const float* __restrict__ input, const float* __restrict__ W1,
                         const float* __restrict__ b1) {
    __shared__ float inp[DD];
    int blk = blockIdx.x, tid = threadIdx.x;
    inp[tid] = input[blk * DD + tid];
    inp[tid + 256] = input[blk * DD + tid + 256];
    __syncthreads();
    for (int a = tid; a < DD; a += 256) {
        const float* w = W1 + (size_t)a * (2 * DD);
        float acc = b1[a];
        #pragma unroll 8
        for (int d = 0; d < DD; d++) acc += inp[d] * w[d];
        g_u[blk * DD + a] = acc;
    }
}

// ==================== prep: W fp16 round ====================
__global__ void prep_w_k(const float* __restrict__ W1) {
    int base = blockIdx.x * 16384, tid = threadIdx.x;
    for (int i = tid; i < 16384; i += 256) {
        int idx = base + i;
        int a = idx >> 9, j = idx & 511;
        g_whi[idx] = __float2half_rn(W1[(size_t)a * (2 * DD) + DD + j]);
    }
}

__global__ void dummy_k() {}

// ==== GEMM (fp16, 16 warps 4x4, group-private B pipelines) + fused score epilogue ====
__global__ void __launch_bounds__(512, 1)
gemm_k(const float* __restrict__ src, float* __restrict__ scores, const float* __restrict__ W2) {
    extern __shared__ char sm[];
    uint32_t smb = smem_u32(sm);
    int tid = threadIdx.x, lid = tid & 31, wid = tid >> 5;
    int wm = wid & 3, wn = wid >> 2;      // 4 m-warps x 4 n-warp-groups
    int gtid = tid & 127;                 // thread-in-group
    int b = blockIdx.y;
    int s0 = blockIdx.x * 128;

    float* u_sm  = (float*)(sm + U_OFF);
    float* w2_sm = (float*)(sm + W2_OFF);
    u_sm[tid] = g_u[b * DD + tid];
    w2_sm[tid] = W2[tid];

    const float* srcb = src + (size_t)b * DD;   // src[s][b][d]; s-stride = BB*DD

    // ---- load + convert entire A tile (128 x 512 fp32 -> fp16) into smem, once ----
    {
        const int c4 = tid & 127;
        const int rb = tid >> 7;              // 0..3
        #pragma unroll 1
        for (int t8 = 0; t8 < 4; t8++) {
            float4 v[8];
            #pragma unroll
            for (int j = 0; j < 8; j++) {
                int r = rb + 4 * (t8 * 8 + j);
                v[j] = *(const float4*)(srcb + (size_t)(s0 + r) * (BB * DD) + c4 * 4);
            }
            #pragma unroll
            for (int j = 0; j < 8; j++) {
                int r = rb + 4 * (t8 * 8 + j);
                *(uint2*)(sm + A_O + r * A_ROWB + c4 * 8) = make_uint2(
                    packh2(__float2half_rn(v[j].x), __float2half_rn(v[j].y)),
                    packh2(__float2half_rn(v[j].z), __float2half_rn(v[j].w)));
            }
        }
    }

    // ---- group-private B pipeline: this group's 32 n-rows only ----
    const int brow = gtid >> 3, bsg = gtid & 7;   // row 0..15 (t adds 16), seg 0..7
    const uint32_t bdst_lane = smb + B_O + (uint32_t)(wn * GST + brow * ROWB2 + bsg * 16);
    const __half* bsrc_lane = g_whi + (size_t)(wn * 32 + brow) * DD + bsg * 8;

    // prologue: stages 0,1  (f = global chunk index; fnt = f>>3, fck = f&7)
    #pragma unroll
    for (int f = 0; f < NSTAGE - 1; f++) {
        int fnt = f >> 3, fck = f & 7;
        const __half* wsrc = bsrc_lane + (size_t)(fnt * 128) * DD + fck * 64;
        uint32_t dst = bdst_lane + f * STG_ALL;
        cp16(dst, wsrc);
        cp16(dst + 16 * ROWB2, wsrc + (size_t)16 * DD);
        asm volatile("cp.async.commit_group;" ::: "memory");
    }
    __syncthreads();   // A tile + u/w2 visible to everyone

    // hoisted LDSM lane addressing
    const uint32_t a_base = smb + A_O + (uint32_t)((wm * 32 + (lid & 15)) * A_ROWB + (lid >> 4) * 16);
    const uint32_t b_lane = (uint32_t)(((((lid >> 4) << 3) | (lid & 7)) * ROWB2) + ((lid >> 3) & 1) * 16);
    const uint32_t b_grp  = smb + B_O + (uint32_t)(wn * GST) + b_lane;

    float sc[4] = {0.f, 0.f, 0.f, 0.f};
    float acc[2][4][4];
    #pragma unroll
    for (int i = 0; i < 2; i++)
        #pragma unroll
        for (int j = 0; j < 4; j++)
            #pragma unroll
            for (int k = 0; k < 4; k++) acc[i][j][k] = 0.f;

    int st = 0, fst = NSTAGE - 1;
    for (int idx = 0; idx < 32; idx++) {
        int nt = idx >> 3, ck = idx & 7;

        asm volatile("cp.async.wait_group %0;" :: "n"(NSTAGE - 2) : "memory");
        BARG(wn + 1);   // group-scoped barrier: B stage visible within this group

        // prefetch chunk idx+2 into stage fst (always-commit keeps accounting exact)
        {
            int f = idx + NSTAGE - 1;
            if (f < 32) {
                int fnt = f >> 3, fck = f & 7;
                const __half* wsrc = bsrc_lane + (size_t)(fnt * 128) * DD + fck * 64;
                uint32_t dst = bdst_lane + fst * STG_ALL;
                cp16(dst, wsrc);
                cp16(dst + 16 * ROWB2, wsrc + (size_t)16 * DD);
            }
            asm volatile("cp.async.commit_group;" ::: "memory");
        }

        // ---- MMA: A persistent, B from group stage (k = 64 per idx) ----
        {
            uint32_t a_ck = a_base + (uint32_t)(ck * 128);
            uint32_t b_st = b_grp + (uint32_t)(st * STG_ALL);
            #pragma unroll
            for (int ks = 0; ks < 4; ks++) {
                uint32_t af[2][4];
                uint32_t aoff = a_ck + (uint32_t)(ks * 32);
                LDSM4(af[0], aoff);
                LDSM4(af[1], aoff + 16 * A_ROWB);
                #pragma unroll
                for (int p = 0; p < 2; p++) {
                    uint32_t bh[4];
                    LDSM4(bh, b_st + (uint32_t)(p * (16 * ROWB2) + ks * 32));
                    #pragma unroll
                    for (int mt = 0; mt < 2; mt++) {
                        MMA(acc[mt][2 * p],     af[mt], bh);
                        MMA(acc[mt][2 * p + 1], af[mt], bh + 2);
                    }
                }
            }
        }
        st = (st == NSTAGE - 1) ? 0 : st + 1;
        fst = (fst == NSTAGE - 1) ? 0 : fst + 1;

        // ---- nt boundary: fold acc into score partials, reset ----
        if (ck == 7) {
            int tq = lid & 3;
            float part[4] = {0.f, 0.f, 0.f, 0.f};
            #pragma unroll
            for (int j = 0; j < 4; j++) {
                int a = nt * 128 + wn * 32 + j * 8 + tq * 2;
                float u0 = u_sm[a], u1 = u_sm[a + 1];
                float w0 = w2_sm[a], w1 = w2_sm[a + 1];
                #pragma unroll
                for (int mt = 0; mt < 2; mt++) {
                    part[mt * 2 + 0] += w0 * tanh_f(acc[mt][j][0] + u0)
                                      + w1 * tanh_f(acc[mt][j][1] + u1);
                    part[mt * 2 + 1] += w0 * tanh_f(acc[mt][j][2] + u0)
                                      + w1 * tanh_f(acc[mt][j][3] + u1);
                }
            }
            #pragma unroll
            for (int i = 0; i < 4; i++) {
                part[i] += __shfl_xor_sync(0xffffffffu, part[i], 1);
                part[i] += __shfl_xor_sync(0xffffffffu, part[i], 2);
                sc[i] += part[i];
            }
            #pragma unroll
            for (int i = 0; i < 2; i++)
                #pragma unroll
                for (int j = 0; j < 4; j++)
                    #pragma unroll
                    for (int k = 0; k < 4; k++) acc[i][j][k] = 0.f;
        }
    }

    // ---- cross-warp (4 n-warp planes) reduction + store scores ----
    float* red = (float*)(sm + RED_OFF);
    __syncthreads();
    if ((lid & 3) == 0) {
        int g = lid >> 2;
        #pragma unroll
        for (int mt = 0; mt < 2; mt++) {
            red[wn * 128 + wm * 32 + mt * 16 + g]     = sc[mt * 2 + 0];
            red[wn * 128 + wm * 32 + mt * 16 + 8 + g] = sc[mt * 2 + 1];
        }
    }
    __syncthreads();
    if (tid < 128)
        scores[(size_t)(s0 + tid) * BB + b] =
            (red[tid] + red[128 + tid]) + (red[256 + tid] + red[384 + tid]);
}

// ==================== softmax over S (in place) ====================
__global__ void softmax_k(float* __restrict__ attn, const unsigned char* __restrict__ mask) {
    __shared__ float red[256];
    int b = blockIdx.x, tid = threadIdx.x;
    float v[8];
    float mx = -1e30f;
    #pragma unroll
    for (int i = 0; i < 8; i++) {
        int s = tid + i * 256;
        float x = attn[(size_t)s * BB + b];
        if (mask[(size_t)s * BB + b]) x = -1e30f;
        v[i] = x;
        mx = fmaxf(mx, x);
    }
    red[tid] = mx; __syncthreads();
    for (int o = 128; o > 0; o >>= 1) { if (tid < o) red[tid] = fmaxf(red[tid], red[tid + o]); __syncthreads(); }
    mx = red[0]; __syncthreads();
    float sum = 0.f;
    #pragma unroll
    for (int i = 0; i < 8; i++) { v[i] = __expf(v[i] - mx); sum += v[i]; }
    red[tid] = sum; __syncthreads();
    for (int o = 128; o > 0; o >>= 1) { if (tid < o) red[tid] += red[tid + o]; __syncthreads(); }
    float inv = __fdividef(1.f, red[0]);
    #pragma unroll
    for (int i = 0; i < 8; i++) attn[(size_t)(tid + i * 256) * BB + b] = v[i] * inv;
}

// ==================== ctx = sum_s attn[s,b] * src[s,b,:]  (float4, deep MLP) ====================
__global__ void ctx_k(const float* __restrict__ src, const float* __restrict__ attn) {
    int b = blockIdx.x, sch = blockIdx.y, tid = threadIdx.x;   // 128 thr, grid (BB, 8)
    const float4* sp = (const float4*)(src + (size_t)b * DD) + tid;
    int s0 = sch * 256;
    float4 a[8];
    #pragma unroll
    for (int j = 0; j < 8; j++) a[j] = make_float4(0.f, 0.f, 0.f, 0.f);
    #pragma unroll 2
    for (int s = s0; s < s0 + 256; s += 8) {
        #pragma unroll
        for (int j = 0; j < 8; j++) {
            float w = attn[(size_t)(s + j) * BB + b];
            float4 v = sp[(size_t)(s + j) * (BB * DD / 4)];
            a[j].x += w * v.x; a[j].y += w * v.y; a[j].z += w * v.z; a[j].w += w * v.w;
        }
    }
    float4 t;
    t.x = ((a[0].x + a[1].x) + (a[2].x + a[3].x)) + ((a[4].x + a[5].x) + (a[6].x + a[7].x));
    t.y = ((a[0].y + a[1].y) + (a[2].y + a[3].y)) + ((a[4].y + a[5].y) + (a[6].y + a[7].y));
    t.z = ((a[0].z + a[1].z) + (a[2].z + a[3].z)) + ((a[4].z + a[5].z) + (a[6].z + a[7].z));
    t.w = ((a[0].w + a[1].w) + (a[2].w + a[3].w)) + ((a[4].w + a[5].w) + (a[6].w + a[7].w));
    ((float4*)g_part)[((sch * BB + b) << 7) + tid] = t;
}

__global__ void red_k(float* __restrict__ out) {
    int i = blockIdx.x * 512 + threadIdx.x;
    float s = 0.f;
    #pragma unroll
    for (int j = 0; j < 8; j++) s += g_part[j * (BB * DD) + i];
    out[i] = s;
}

// ==================== launch ====================
extern "C" void kernel_launch(void* const* d_in, const int* in_sizes, int n_in,
                              void* d_out, int out_size) {
    (void)in_sizes; (void)n_in; (void)out_size;
    const float* input = (const float*)d_in[0];
    const float* src = (const float*)d_in[1];
    const unsigned char* mask = (const unsigned char*)d_in[2];
    const float* W1 = (const float*)d_in[3];
    const float* b1 = (const float*)d_in[4];
    const float* W2 = (const float*)d_in[5];
    float* out = (float*)d_out;          // [ctx: 64*512][attn: 2048*64]
    float* attn = out + BB * DD;

    cudaFuncSetAttribute(gemm_k, cudaFuncAttributeMaxDynamicSharedMemorySize, DYN_SMEM);

    prep_u_k<<<BB, 256>>>(input, W1, b1);        // launch 1
    prep_w_k<<<16, 256>>>(W1);                   // launch 2
    dummy_k<<<1, 32>>>();                        // launch 3
    gemm_k<<<dim3(16, BB), 512, DYN_SMEM>>>(src, attn, W2);   // launch 4
    softmax_k<<<BB, 256>>>(attn, mask);
    ctx_k<<<dim3(BB, 8), 128>>>(src, attn);
    red_k<<<BB, 512>>>(out);
}